// round 14
// baseline (speedup 1.0000x reference)
#include <cuda_runtime.h>
#include <math.h>

#define Ln 8192
#define Hn 256
#define Bn 16
#define Pn 64

// Krs spectrum, bit-reversed order per h.
__device__ float4 g_Krs4[Hn * Ln / 2];   // 16MB

#define TWO_PI 6.283185307179586f

typedef unsigned long long u64t;

#define FMA_F32X2(d, a, b, c) \
    asm("fma.rn.f32x2 %0, %1, %2, %3;" : "=l"(d) : "l"(a), "l"(b), "l"(c))
#define PACK_F32X2(out, lo, hi) \
    asm("mov.b64 %0, {%1, %2};" : "=l"(out) : "r"(lo), "r"(hi))

__device__ __forceinline__ float f2lo(u64t v) { return __uint_as_float((unsigned)v); }
__device__ __forceinline__ float f2hi(u64t v) { return __uint_as_float((unsigned)(v >> 32)); }

__device__ __forceinline__ float2 cmul(float2 a, float2 b) {
    return make_float2(a.x * b.x - a.y * b.y, a.x * b.y + a.y * b.x);
}
__device__ __forceinline__ float2 cadd(float2 a, float2 b) { return make_float2(a.x + b.x, a.y + b.y); }
__device__ __forceinline__ float2 csub(float2 a, float2 b) { return make_float2(a.x - b.x, a.y - b.y); }
__device__ __forceinline__ float2 mulnegI(float2 a) { return make_float2(a.y, -a.x); }
__device__ __forceinline__ float2 mulposI(float2 a) { return make_float2(-a.y, a.x); }
__device__ __forceinline__ float2 conjf2(float2 a) { return make_float2(a.x, -a.y); }

// e^{i*2*pi*t} via fast MUFU trig; t re-centered to (-0.5, 0.5].
__device__ __forceinline__ float2 cis2pi(float t) {
    t -= rintf(t);
    float s, c; __sincosf(TWO_PI * t, &s, &c);
    return make_float2(c, s);
}

__device__ __forceinline__ float ftanh(float x) {
    float e = __expf(2.f * x);
    return 1.f - __fdividef(2.f, e + 1.f);
}

// ---------------------------------------------------------------------------
// Kernel 1: Krs_br[h, q] = Krs[h, bitrev13(q)].
//   Krs[h,f] = sum_p ( alpha - beta w ) / (1 - 2Re(A) w + |A|^2 w^2 )
// MAC uses packed fma.rn.f32x2: acc(re,im) += (a,a)*(Sr,Si) + (-b,-b)*(Qr,Qi).
// Layout: lane = h (per-lane ab, packs amortized), fj warp-uniform (G broadcast).
// ---------------------------------------------------------------------------
__global__ void __launch_bounds__(512) kernel_spectrum(
    const float* __restrict__ A_re, const float* __restrict__ A_im,
    const float* __restrict__ BC_re, const float* __restrict__ BC_im)
{
    extern __shared__ char smemK[];
    float4* G4  = (float4*)smemK;                // [64 p][64 fj]        64KB
    float2* AB2 = (float2*)(smemK + 65536);      // [64 p][64 h] (a,-b)  32KB

    int t = threadIdx.x;
    int h0 = blockIdx.y * 64;
    int f0c = blockIdx.x;              // 0..64
    bool has_mirror = (f0c != 0) && (f0c != 64);

    // Phase 1: resolvent tile (1/d, w/d), accurate trig (denoms can be small).
    for (int idx = t; idx < 4096; idx += 512) {
        int p = idx >> 6, fj = idx & 63;
        int f = f0c + 128 * fj;
        int fm = (f > 4096) ? f - Ln : f;
        float ang = (TWO_PI / (float)Ln) * (float)fm;
        float sn, cs; sincosf(ang, &sn, &cs);
        float wr = cs, wi = -sn;
        float Ar = A_re[p], Ai = A_im[p];
        float g = 2.f * Ar;
        float dl = Ar * Ar + Ai * Ai;
        float w2r = wr * wr - wi * wi;
        float w2i = 2.f * wr * wi;
        float dr = 1.f - g * wr + dl * w2r;
        float di = -g * wi + dl * w2i;
        float iv = 1.f / (dr * dr + di * di);
        float cr = dr * iv, ci = -di * iv;        // 1/d
        float qr = wr * cr - wi * ci;             // w/d
        float qi = wr * ci + wi * cr;
        G4[idx] = make_float4(cr, ci, qr, qi);
    }
    for (int idx = t; idx < 64 * 64; idx += 512) {
        int hl = idx >> 6, p = idx & 63;
        float br = BC_re[(h0 + hl) * Pn + p];
        float bi = BC_im[(h0 + hl) * Pn + p];
        float Ar = A_re[p], Ai = A_im[p];
        AB2[p * 64 + hl] = make_float2(br, -(br * Ar + bi * Ai));
    }
    __syncthreads();

    // MAC: lane = h, fj warp-uniform.
    int lane = t & 31, w = t >> 5;
    int hl = lane + ((w & 1) << 5);   // 64 h across warp-halves
    int fg = w >> 1;                  // 8 fj per thread: fg*8 + j
    u64t acc[8];
#pragma unroll
    for (int j = 0; j < 8; j++) acc[j] = 0ull;

    const ulonglong2* G2 = (const ulonglong2*)G4;
#pragma unroll 2
    for (int p = 0; p < 64; p++) {
        float2 ab = AB2[p * 64 + hl];
        u64t paa, pbb;
        PACK_F32X2(paa, __float_as_uint(ab.x), __float_as_uint(ab.x));
        PACK_F32X2(pbb, __float_as_uint(ab.y), __float_as_uint(ab.y));
#pragma unroll
        for (int j = 0; j < 8; j++) {
            ulonglong2 g = G2[p * 64 + fg * 8 + j];   // broadcast LDS.128
            FMA_F32X2(acc[j], paa, g.x, acc[j]);      // (a,a)*(Sr,Si)
            FMA_F32X2(acc[j], pbb, g.y, acc[j]);      // (-b,-b)*(Qr,Qi)
        }
    }
    __syncthreads();

    // Stage [q][h] with pitch 65 (aliases dead G4/AB2), then coalesced store.
    float2* stg1 = (float2*)smemK;               // [64 q][65]
    float2* stg2 = stg1 + 64 * 65;               // mirror (conj)
#pragma unroll
    for (int j = 0; j < 8; j++) {
        int fj = fg * 8 + j;
        int off = (int)(__brev((unsigned)fj) >> 26);   // brev6(fj)
        float re = f2lo(acc[j]), im = f2hi(acc[j]);
        stg1[off * 65 + hl] = make_float2(re, im);
        if (has_mirror)
            stg2[(63 - off) * 65 + hl] = make_float2(re, -im);
    }
    __syncthreads();

    float2* Krs = (float2*)g_Krs4;
    int qb1 = (int)(__brev((unsigned)f0c) >> 25) * 64;   // brev7(f0c)*64
    for (int idx = t; idx < 4096; idx += 512) {
        int h = idx >> 6, q = idx & 63;
        Krs[(size_t)(h0 + h) * Ln + qb1 + q] = stg1[q * 65 + h];
    }
    if (has_mirror) {
        int qb2 = (int)(__brev((unsigned)(128 - f0c)) >> 25) * 64;
        for (int idx = t; idx < 4096; idx += 512) {
            int h = idx >> 6, q = idx & 63;
            Krs[(size_t)(h0 + h) * Ln + qb2 + q] = stg2[q * 65 + h];
        }
    }
}

// ---------------------------------------------------------------------------
// Kernel 2: FFT conv main. 13 stages = radix16(ends) + radix8(mid) + 8-contig F5.
// Skew i + 2*(i>>4): 8-blocks are 16B-aligned -> float4 LDS/STS in F5.
// (unchanged from round 12 — best measured)
// ---------------------------------------------------------------------------
#define SKB(i) ((i) + (((i) >> 4) << 1))
#define RHv 0.70710678118654752f
#define C16v 0.92387953251128675f   // cos(pi/8)
#define S16v 0.38268343236508977f   // sin(pi/8)

__device__ __forceinline__ void bf_dif(float2& a, float2& b, float2 w) {
    float2 t = csub(a, b); a = cadd(a, b); b = cmul(t, w);
}
__device__ __forceinline__ void bf_dit(float2& a, float2& b, float2 w) {
    float2 t = cmul(b, w); b = csub(a, t); a = cadd(a, t);
}
__device__ __forceinline__ void bf1_dif(float2& a, float2& b) {
    float2 t = csub(a, b); a = cadd(a, b); b = t;
}
__device__ __forceinline__ void bf1_dit(float2& a, float2& b) {
    float2 t = b; b = csub(a, t); a = cadd(a, t);
}

// 3 DIF radix-2 stages (m = 8s, 4s, 2s); twiddle base w1.
__device__ __forceinline__ void fwd8w(float2* p, float2 w1) {
    float2 w2 = cmul(w1, w1);
    float2 w4 = cmul(w2, w2);
    float2 w1b = cmul(w1, make_float2(RHv, -RHv));
    bf_dif(p[0], p[4], w1);
    bf_dif(p[1], p[5], w1b);
    bf_dif(p[2], p[6], mulnegI(w1));
    bf_dif(p[3], p[7], mulnegI(w1b));
    float2 w2b = mulnegI(w2);
    bf_dif(p[0], p[2], w2);  bf_dif(p[1], p[3], w2b);
    bf_dif(p[4], p[6], w2);  bf_dif(p[5], p[7], w2b);
    bf_dif(p[0], p[1], w4);  bf_dif(p[2], p[3], w4);
    bf_dif(p[4], p[5], w4);  bf_dif(p[6], p[7], w4);
}

// 3 DIT radix-2 stages (m = 2s, 4s, 8s); inverse twiddle base v1.
__device__ __forceinline__ void inv8w(float2* p, float2 v1) {
    float2 v2 = cmul(v1, v1);
    float2 v4 = cmul(v2, v2);
    bf_dit(p[0], p[1], v4);  bf_dit(p[2], p[3], v4);
    bf_dit(p[4], p[5], v4);  bf_dit(p[6], p[7], v4);
    float2 v2b = mulposI(v2);
    bf_dit(p[0], p[2], v2);  bf_dit(p[1], p[3], v2b);
    bf_dit(p[4], p[6], v2);  bf_dit(p[5], p[7], v2b);
    float2 v1b = cmul(v1, make_float2(RHv, RHv));
    bf_dit(p[0], p[4], v1);
    bf_dit(p[1], p[5], v1b);
    bf_dit(p[2], p[6], mulposI(v1));
    bf_dit(p[3], p[7], mulposI(v1b));
}

// 4 DIF stages over 16 points at one stride; base twiddle w1.
__device__ __forceinline__ void fwd16w(float2* p, float2 w1) {
    float2 a1 = cmul(w1, make_float2(C16v, -S16v));
    float2 a2 = cmul(w1, make_float2(RHv, -RHv));
    float2 a3 = cmul(w1, make_float2(S16v, -C16v));
    bf_dif(p[0], p[8],  w1);
    bf_dif(p[1], p[9],  a1);
    bf_dif(p[2], p[10], a2);
    bf_dif(p[3], p[11], a3);
    bf_dif(p[4], p[12], mulnegI(w1));
    bf_dif(p[5], p[13], mulnegI(a1));
    bf_dif(p[6], p[14], mulnegI(a2));
    bf_dif(p[7], p[15], mulnegI(a3));
    float2 w2 = cmul(w1, w1);
    fwd8w(p, w2);
    fwd8w(p + 8, w2);
}

// 4 DIT stages over 16 points at one stride; inverse base twiddle v1.
__device__ __forceinline__ void inv16w(float2* p, float2 v1) {
    float2 v2 = cmul(v1, v1);
    inv8w(p, v2);
    inv8w(p + 8, v2);
    float2 b1 = cmul(v1, make_float2(C16v, S16v));
    float2 b2 = cmul(v1, make_float2(RHv, RHv));
    float2 b3 = cmul(v1, make_float2(S16v, C16v));
    bf_dit(p[0], p[8],  v1);
    bf_dit(p[1], p[9],  b1);
    bf_dit(p[2], p[10], b2);
    bf_dit(p[3], p[11], b3);
    bf_dit(p[4], p[12], mulposI(v1));
    bf_dit(p[5], p[13], mulposI(b1));
    bf_dit(p[6], p[14], mulposI(b2));
    bf_dit(p[7], p[15], mulposI(b3));
}

// Constant-twiddle contiguous 8-point DIF (m=8,4,2), r=0.
__device__ __forceinline__ void fwd8_r0(float2* p) {
    bf1_dif(p[0], p[4]);
    bf_dif(p[1], p[5], make_float2(RHv, -RHv));
    { float2 t = csub(p[2], p[6]); p[2] = cadd(p[2], p[6]); p[6] = mulnegI(t); }
    bf_dif(p[3], p[7], make_float2(-RHv, -RHv));
    bf1_dif(p[0], p[2]);
    { float2 t = csub(p[1], p[3]); p[1] = cadd(p[1], p[3]); p[3] = mulnegI(t); }
    bf1_dif(p[4], p[6]);
    { float2 t = csub(p[5], p[7]); p[5] = cadd(p[5], p[7]); p[7] = mulnegI(t); }
    bf1_dif(p[0], p[1]); bf1_dif(p[2], p[3]);
    bf1_dif(p[4], p[5]); bf1_dif(p[6], p[7]);
}

// Constant-twiddle contiguous 8-point DIT (m=2,4,8), r=0.
__device__ __forceinline__ void inv8_r0(float2* p) {
    bf1_dit(p[0], p[1]); bf1_dit(p[2], p[3]);
    bf1_dit(p[4], p[5]); bf1_dit(p[6], p[7]);
    bf1_dit(p[0], p[2]);
    { float2 t = mulposI(p[3]); p[3] = csub(p[1], t); p[1] = cadd(p[1], t); }
    bf1_dit(p[4], p[6]);
    { float2 t = mulposI(p[7]); p[7] = csub(p[5], t); p[5] = cadd(p[5], t); }
    bf1_dit(p[0], p[4]);
    bf_dit(p[1], p[5], make_float2(RHv, RHv));
    { float2 t = mulposI(p[6]); p[6] = csub(p[2], t); p[2] = cadd(p[2], t); }
    bf_dit(p[3], p[7], make_float2(-RHv, RHv));
}

// Radix-8 shared pass: lut[r] = e^{-2pi i r/(8S)}.
template <int S, int LS, bool FWD>
__device__ __forceinline__ void shared_pass(float2* z, const float2* lut, int tid) {
#pragma unroll
    for (int it2 = 0; it2 < 2; it2++) {
        int it = tid + it2 * 512;
        int r = it & (S - 1);
        int base = ((it >> LS) << (LS + 3)) + r;
        float2 w1 = lut[r];
        if (!FWD) w1 = conjf2(w1);
        float2 p[8];
#pragma unroll
        for (int c = 0; c < 8; c++) p[c] = z[SKB(base + c * S)];
        if (FWD) fwd8w(p, w1);
        else     inv8w(p, w1);
#pragma unroll
        for (int c = 0; c < 8; c++) z[SKB(base + c * S)] = p[c];
    }
}

__global__ void __launch_bounds__(512, 2) fftconv_main(
    const float* __restrict__ u, const float* __restrict__ D,
    float* __restrict__ out)
{
    extern __shared__ float2 sm[];
    float2* lutA = sm;                 // 512 : e^{-2pi i r/8192}, r<512
    float2* lutB = sm + 512;           // 64  : e^{-2pi i r/512}
    float2* lutC = sm + 576;           // 8   : e^{-2pi i r/64}
    float2* zc   = sm + 584;           // 9216 float2 (skewed 8192)

    int blk = blockIdx.x;
    int h = blk >> 3, pb = blk & 7;
    const float* u1 = u + ((size_t)(2 * pb) * Hn + h) * Ln;
    const float* u2 = u + ((size_t)(2 * pb + 1) * Hn + h) * Ln;
    float* o1 = out + ((size_t)(2 * pb) * Hn + h) * Ln;
    float* o2 = out + ((size_t)(2 * pb + 1) * Hn + h) * Ln;
    int tid = threadIdx.x;

    // Twiddle LUT init
    lutA[tid] = cis2pi(-(float)tid * (1.f / 8192.f));
    if (tid < 64) lutB[tid] = cis2pi(-(float)tid * (1.f / 512.f));
    if (tid < 8)  lutC[tid] = cis2pi(-(float)tid * (1.f / 64.f));
    __syncthreads();

    // F1: load z = u1 + i*u2, radix-16 s=512 (m=8192,4096,2048,1024)
    {
        float2 p[16];
#pragma unroll
        for (int c = 0; c < 16; c++) {
            int n = tid + c * 512;
            p[c] = make_float2(u1[n], u2[n]);
        }
        fwd16w(p, lutA[tid]);
#pragma unroll
        for (int c = 0; c < 16; c++) zc[SKB(tid + c * 512)] = p[c];
    }
    __syncthreads();
    shared_pass<64, 6, true>(zc, lutB, tid);   // m = 512,256,128
    __syncthreads();
    shared_pass<8, 3, true>(zc, lutC, tid);    // m = 64,32,16
    __syncthreads();

    // F5: 8 contiguous points: fwd m=8,4,2 -> *Krs(bitrev) -> inv m=2,4,8
    {
        const float4* K4 = g_Krs4 + (size_t)h * (Ln / 2);
        float4* zc4 = (float4*)zc;
#pragma unroll
        for (int it2 = 0; it2 < 2; it2++) {
            int idx = tid + it2 * 512;          // 8-block index
            int s0 = SKB(8 * idx) >> 1;         // float4 index (16B-aligned)
            float2 q[8];
#pragma unroll
            for (int j = 0; j < 4; j++) {
                float4 v = zc4[s0 + j];
                q[2 * j]     = make_float2(v.x, v.y);
                q[2 * j + 1] = make_float2(v.z, v.w);
            }
            fwd8_r0(q);
#pragma unroll
            for (int j = 0; j < 4; j++) {
                float4 kk = __ldg(&K4[4 * idx + j]);
                q[2 * j]     = cmul(q[2 * j],     make_float2(kk.x, kk.y));
                q[2 * j + 1] = cmul(q[2 * j + 1], make_float2(kk.z, kk.w));
            }
            inv8_r0(q);
#pragma unroll
            for (int j = 0; j < 4; j++)
                zc4[s0 + j] = make_float4(q[2 * j].x, q[2 * j].y,
                                          q[2 * j + 1].x, q[2 * j + 1].y);
        }
    }
    __syncthreads();
    shared_pass<8, 3, false>(zc, lutC, tid);   // m = 16,32,64
    __syncthreads();
    shared_pass<64, 6, false>(zc, lutB, tid);  // m = 128,256,512
    __syncthreads();

    // I1: radix-16 s=512 (m=1024..8192), scale, D-skip (u reloaded), tanh
    {
        float Dh = D[h];
        const float sc = 1.f / 8192.f;
        float2 p[16];
#pragma unroll
        for (int c = 0; c < 16; c++) p[c] = zc[SKB(tid + c * 512)];
        inv16w(p, conjf2(lutA[tid]));
#pragma unroll
        for (int c = 0; c < 16; c++) {
            int n = tid + c * 512;
            o1[n] = ftanh(p[c].x * sc + Dh * u1[n]);
            o2[n] = ftanh(p[c].y * sc + Dh * u2[n]);
        }
    }
}

extern "C" void kernel_launch(void* const* d_in, const int* in_sizes, int n_in,
                              void* d_out, int out_size)
{
    const float* u     = (const float*)d_in[0];
    const float* A_re  = (const float*)d_in[1];
    const float* A_im  = (const float*)d_in[2];
    const float* BC_re = (const float*)d_in[3];
    const float* BC_im = (const float*)d_in[4];
    const float* D     = (const float*)d_in[5];

    const int MAIN_SMEM = (584 + 9216) * 8;   // 78400 bytes

    cudaFuncSetAttribute(kernel_spectrum, cudaFuncAttributeMaxDynamicSharedMemorySize, 98304);
    cudaFuncSetAttribute(fftconv_main, cudaFuncAttributeMaxDynamicSharedMemorySize, MAIN_SMEM);

    kernel_spectrum<<<dim3(65, 4), 512, 98304>>>(A_re, A_im, BC_re, BC_im);
    fftconv_main<<<Bn / 2 * Hn, 512, MAIN_SMEM>>>(u, D, (float*)d_out);
}

// round 15
// speedup vs baseline: 1.0131x; 1.0131x over previous
#include <cuda_runtime.h>
#include <math.h>

#define Ln 8192
#define Hn 256
#define Bn 16
#define Pn 64

// Krs spectrum, bit-reversed order per h.
__device__ float4 g_Krs4[Hn * Ln / 2];   // 16MB

#define TWO_PI 6.283185307179586f

__device__ __forceinline__ float2 cmul(float2 a, float2 b) {
    return make_float2(a.x * b.x - a.y * b.y, a.x * b.y + a.y * b.x);
}
__device__ __forceinline__ float2 cadd(float2 a, float2 b) { return make_float2(a.x + b.x, a.y + b.y); }
__device__ __forceinline__ float2 csub(float2 a, float2 b) { return make_float2(a.x - b.x, a.y - b.y); }
__device__ __forceinline__ float2 mulnegI(float2 a) { return make_float2(a.y, -a.x); }
__device__ __forceinline__ float2 mulposI(float2 a) { return make_float2(-a.y, a.x); }
__device__ __forceinline__ float2 conjf2(float2 a) { return make_float2(a.x, -a.y); }

// e^{i*2*pi*t} via fast MUFU trig; t re-centered to (-0.5, 0.5].
__device__ __forceinline__ float2 cis2pi(float t) {
    t -= rintf(t);
    float s, c; __sincosf(TWO_PI * t, &s, &c);
    return make_float2(c, s);
}

__device__ __forceinline__ float ftanh(float x) {
    float e = __expf(2.f * x);
    return 1.f - __fdividef(2.f, e + 1.f);
}

// ---------------------------------------------------------------------------
// Kernel 1: Krs_br[h, q] = Krs[h, bitrev13(q)]  (round-12 version — 27.5us
// measured; f32x2 variant reverted: it halved FFMA but doubled LDS issue)
// ---------------------------------------------------------------------------
__global__ void __launch_bounds__(512) kernel_spectrum(
    const float* __restrict__ A_re, const float* __restrict__ A_im,
    const float* __restrict__ BC_re, const float* __restrict__ BC_im)
{
    extern __shared__ char smemK[];
    float4* G4  = (float4*)smemK;                // [64 p][64 fj]        64KB
    float4* ABT = (float4*)(smemK + 65536);      // [64 p][32 h-pairs]   32KB

    int t = threadIdx.x;
    int h0 = blockIdx.y * 64;
    int f0c = blockIdx.x;              // 0..64
    bool has_mirror = (f0c != 0) && (f0c != 64);

    for (int idx = t; idx < 4096; idx += 512) {
        int p = idx >> 6, fj = idx & 63;
        int f = f0c + 128 * fj;
        int fm = (f > 4096) ? f - Ln : f;
        float ang = (TWO_PI / (float)Ln) * (float)fm;
        float sn, cs; sincosf(ang, &sn, &cs);
        float wr = cs, wi = -sn;
        float Ar = A_re[p], Ai = A_im[p];
        float g = 2.f * Ar;
        float dl = Ar * Ar + Ai * Ai;
        float w2r = wr * wr - wi * wi;
        float w2i = 2.f * wr * wi;
        float dr = 1.f - g * wr + dl * w2r;
        float di = -g * wi + dl * w2i;
        float iv = 1.f / (dr * dr + di * di);
        float cr = dr * iv, ci = -di * iv;        // 1/d
        float qr = wr * cr - wi * ci;             // w/d
        float qi = wr * ci + wi * cr;
        G4[idx] = make_float4(cr, ci, qr, qi);
    }
    for (int idx = t; idx < 64 * 64; idx += 512) {
        int hl = idx >> 6, p = idx & 63;
        float br = BC_re[(h0 + hl) * Pn + p];
        float bi = BC_im[(h0 + hl) * Pn + p];
        float Ar = A_re[p], Ai = A_im[p];
        ((float2*)ABT)[p * 64 + hl] = make_float2(br, -(br * Ar + bi * Ai));
    }
    __syncthreads();

    int tx = t & 63, tg = t >> 6;   // tx = fj; tg in [0,8): 8 h each
    float2 acc[8];
#pragma unroll
    for (int i = 0; i < 8; i++) acc[i] = make_float2(0.f, 0.f);

#pragma unroll 4
    for (int p = 0; p < 64; p++) {
        float4 g = G4[p * 64 + tx];
#pragma unroll
        for (int i = 0; i < 4; i++) {
            float4 ab2 = ABT[p * 32 + tg * 4 + i];
            acc[2 * i].x     += ab2.x * g.x + ab2.y * g.z;
            acc[2 * i].y     += ab2.x * g.y + ab2.y * g.w;
            acc[2 * i + 1].x += ab2.z * g.x + ab2.w * g.z;
            acc[2 * i + 1].y += ab2.z * g.y + ab2.w * g.w;
        }
    }
    __syncthreads();

    float2* stg1 = (float2*)smemK;               // [64 h][64 q]
    float2* stg2 = stg1 + 4096;                  // mirror (conj)
    int off = (int)(__brev((unsigned)tx) >> 26); // brev6(fj)
#pragma unroll
    for (int i = 0; i < 8; i++) {
        int row = tg * 8 + i;
        stg1[row * 64 + off] = acc[i];
        if (has_mirror)
            stg2[row * 64 + (63 - off)] = make_float2(acc[i].x, -acc[i].y);
    }
    __syncthreads();

    float2* Krs = (float2*)g_Krs4;
    int qb1 = (int)(__brev((unsigned)f0c) >> 25) * 64;
    for (int idx = t; idx < 4096; idx += 512) {
        int h = idx >> 6;
        Krs[(size_t)(h0 + h) * Ln + qb1 + (idx & 63)] = stg1[idx];
    }
    if (has_mirror) {
        int qb2 = (int)(__brev((unsigned)(128 - f0c)) >> 25) * 64;
        for (int idx = t; idx < 4096; idx += 512) {
            int h = idx >> 6;
            Krs[(size_t)(h0 + h) * Ln + qb2 + (idx & 63)] = stg2[idx];
        }
    }
}

// ---------------------------------------------------------------------------
// Kernel 2: FFT conv main. 13 stages = radix16(ends) + radix8(mid) + 8-contig F5.
// P8 / F5 / P8i exchange stays within aligned 8-thread groups -> the two
// barriers flanking F5 are __syncwarp() (intra-warp smem ordering suffices).
// ---------------------------------------------------------------------------
#define SKB(i) ((i) + (((i) >> 4) << 1))
#define RHv 0.70710678118654752f
#define C16v 0.92387953251128675f   // cos(pi/8)
#define S16v 0.38268343236508977f   // sin(pi/8)

__device__ __forceinline__ void bf_dif(float2& a, float2& b, float2 w) {
    float2 t = csub(a, b); a = cadd(a, b); b = cmul(t, w);
}
__device__ __forceinline__ void bf_dit(float2& a, float2& b, float2 w) {
    float2 t = cmul(b, w); b = csub(a, t); a = cadd(a, t);
}
__device__ __forceinline__ void bf1_dif(float2& a, float2& b) {
    float2 t = csub(a, b); a = cadd(a, b); b = t;
}
__device__ __forceinline__ void bf1_dit(float2& a, float2& b) {
    float2 t = b; b = csub(a, t); a = cadd(a, t);
}

// 3 DIF radix-2 stages (m = 8s, 4s, 2s); twiddle base w1.
__device__ __forceinline__ void fwd8w(float2* p, float2 w1) {
    float2 w2 = cmul(w1, w1);
    float2 w4 = cmul(w2, w2);
    float2 w1b = cmul(w1, make_float2(RHv, -RHv));
    bf_dif(p[0], p[4], w1);
    bf_dif(p[1], p[5], w1b);
    bf_dif(p[2], p[6], mulnegI(w1));
    bf_dif(p[3], p[7], mulnegI(w1b));
    float2 w2b = mulnegI(w2);
    bf_dif(p[0], p[2], w2);  bf_dif(p[1], p[3], w2b);
    bf_dif(p[4], p[6], w2);  bf_dif(p[5], p[7], w2b);
    bf_dif(p[0], p[1], w4);  bf_dif(p[2], p[3], w4);
    bf_dif(p[4], p[5], w4);  bf_dif(p[6], p[7], w4);
}

// 3 DIT radix-2 stages (m = 2s, 4s, 8s); inverse twiddle base v1.
__device__ __forceinline__ void inv8w(float2* p, float2 v1) {
    float2 v2 = cmul(v1, v1);
    float2 v4 = cmul(v2, v2);
    bf_dit(p[0], p[1], v4);  bf_dit(p[2], p[3], v4);
    bf_dit(p[4], p[5], v4);  bf_dit(p[6], p[7], v4);
    float2 v2b = mulposI(v2);
    bf_dit(p[0], p[2], v2);  bf_dit(p[1], p[3], v2b);
    bf_dit(p[4], p[6], v2);  bf_dit(p[5], p[7], v2b);
    float2 v1b = cmul(v1, make_float2(RHv, RHv));
    bf_dit(p[0], p[4], v1);
    bf_dit(p[1], p[5], v1b);
    bf_dit(p[2], p[6], mulposI(v1));
    bf_dit(p[3], p[7], mulposI(v1b));
}

// 4 DIF stages over 16 points at one stride; base twiddle w1.
__device__ __forceinline__ void fwd16w(float2* p, float2 w1) {
    float2 a1 = cmul(w1, make_float2(C16v, -S16v));
    float2 a2 = cmul(w1, make_float2(RHv, -RHv));
    float2 a3 = cmul(w1, make_float2(S16v, -C16v));
    bf_dif(p[0], p[8],  w1);
    bf_dif(p[1], p[9],  a1);
    bf_dif(p[2], p[10], a2);
    bf_dif(p[3], p[11], a3);
    bf_dif(p[4], p[12], mulnegI(w1));
    bf_dif(p[5], p[13], mulnegI(a1));
    bf_dif(p[6], p[14], mulnegI(a2));
    bf_dif(p[7], p[15], mulnegI(a3));
    float2 w2 = cmul(w1, w1);
    fwd8w(p, w2);
    fwd8w(p + 8, w2);
}

// 4 DIT stages over 16 points at one stride; inverse base twiddle v1.
__device__ __forceinline__ void inv16w(float2* p, float2 v1) {
    float2 v2 = cmul(v1, v1);
    inv8w(p, v2);
    inv8w(p + 8, v2);
    float2 b1 = cmul(v1, make_float2(C16v, S16v));
    float2 b2 = cmul(v1, make_float2(RHv, RHv));
    float2 b3 = cmul(v1, make_float2(S16v, C16v));
    bf_dit(p[0], p[8],  v1);
    bf_dit(p[1], p[9],  b1);
    bf_dit(p[2], p[10], b2);
    bf_dit(p[3], p[11], b3);
    bf_dit(p[4], p[12], mulposI(v1));
    bf_dit(p[5], p[13], mulposI(b1));
    bf_dit(p[6], p[14], mulposI(b2));
    bf_dit(p[7], p[15], mulposI(b3));
}

// Constant-twiddle contiguous 8-point DIF (m=8,4,2), r=0.
__device__ __forceinline__ void fwd8_r0(float2* p) {
    bf1_dif(p[0], p[4]);
    bf_dif(p[1], p[5], make_float2(RHv, -RHv));
    { float2 t = csub(p[2], p[6]); p[2] = cadd(p[2], p[6]); p[6] = mulnegI(t); }
    bf_dif(p[3], p[7], make_float2(-RHv, -RHv));
    bf1_dif(p[0], p[2]);
    { float2 t = csub(p[1], p[3]); p[1] = cadd(p[1], p[3]); p[3] = mulnegI(t); }
    bf1_dif(p[4], p[6]);
    { float2 t = csub(p[5], p[7]); p[5] = cadd(p[5], p[7]); p[7] = mulnegI(t); }
    bf1_dif(p[0], p[1]); bf1_dif(p[2], p[3]);
    bf1_dif(p[4], p[5]); bf1_dif(p[6], p[7]);
}

// Constant-twiddle contiguous 8-point DIT (m=2,4,8), r=0.
__device__ __forceinline__ void inv8_r0(float2* p) {
    bf1_dit(p[0], p[1]); bf1_dit(p[2], p[3]);
    bf1_dit(p[4], p[5]); bf1_dit(p[6], p[7]);
    bf1_dit(p[0], p[2]);
    { float2 t = mulposI(p[3]); p[3] = csub(p[1], t); p[1] = cadd(p[1], t); }
    bf1_dit(p[4], p[6]);
    { float2 t = mulposI(p[7]); p[7] = csub(p[5], t); p[5] = cadd(p[5], t); }
    bf1_dit(p[0], p[4]);
    bf_dit(p[1], p[5], make_float2(RHv, RHv));
    { float2 t = mulposI(p[6]); p[6] = csub(p[2], t); p[2] = cadd(p[2], t); }
    bf_dit(p[3], p[7], make_float2(-RHv, RHv));
}

// Radix-8 shared pass: lut[r] = e^{-2pi i r/(8S)}.
template <int S, int LS, bool FWD>
__device__ __forceinline__ void shared_pass(float2* z, const float2* lut, int tid) {
#pragma unroll
    for (int it2 = 0; it2 < 2; it2++) {
        int it = tid + it2 * 512;
        int r = it & (S - 1);
        int base = ((it >> LS) << (LS + 3)) + r;
        float2 w1 = lut[r];
        if (!FWD) w1 = conjf2(w1);
        float2 p[8];
#pragma unroll
        for (int c = 0; c < 8; c++) p[c] = z[SKB(base + c * S)];
        if (FWD) fwd8w(p, w1);
        else     inv8w(p, w1);
#pragma unroll
        for (int c = 0; c < 8; c++) z[SKB(base + c * S)] = p[c];
    }
}

__global__ void __launch_bounds__(512, 2) fftconv_main(
    const float* __restrict__ u, const float* __restrict__ D,
    float* __restrict__ out)
{
    extern __shared__ float2 sm[];
    float2* lutA = sm;                 // 512 : e^{-2pi i r/8192}, r<512
    float2* lutB = sm + 512;           // 64  : e^{-2pi i r/512}
    float2* lutC = sm + 576;           // 8   : e^{-2pi i r/64}
    float2* zc   = sm + 584;           // 9216 float2 (skewed 8192)

    int blk = blockIdx.x;
    int h = blk >> 3, pb = blk & 7;
    const float* u1 = u + ((size_t)(2 * pb) * Hn + h) * Ln;
    const float* u2 = u + ((size_t)(2 * pb + 1) * Hn + h) * Ln;
    float* o1 = out + ((size_t)(2 * pb) * Hn + h) * Ln;
    float* o2 = out + ((size_t)(2 * pb + 1) * Hn + h) * Ln;
    int tid = threadIdx.x;

    // Twiddle LUT init
    lutA[tid] = cis2pi(-(float)tid * (1.f / 8192.f));
    if (tid < 64) lutB[tid] = cis2pi(-(float)tid * (1.f / 512.f));
    if (tid < 8)  lutC[tid] = cis2pi(-(float)tid * (1.f / 64.f));
    __syncthreads();

    // F1: load z = u1 + i*u2, radix-16 s=512 (m=8192,4096,2048,1024)
    {
        float2 p[16];
#pragma unroll
        for (int c = 0; c < 16; c++) {
            int n = tid + c * 512;
            p[c] = make_float2(u1[n], u2[n]);
        }
        fwd16w(p, lutA[tid]);
#pragma unroll
        for (int c = 0; c < 16; c++) zc[SKB(tid + c * 512)] = p[c];
    }
    __syncthreads();
    shared_pass<64, 6, true>(zc, lutB, tid);   // m = 512,256,128
    __syncthreads();
    shared_pass<8, 3, true>(zc, lutC, tid);    // m = 64,32,16
    __syncwarp();                              // exchange within 8-thread groups

    // F5: 8 contiguous points: fwd m=8,4,2 -> *Krs(bitrev) -> inv m=2,4,8
    {
        const float4* K4 = g_Krs4 + (size_t)h * (Ln / 2);
        float4* zc4 = (float4*)zc;
#pragma unroll
        for (int it2 = 0; it2 < 2; it2++) {
            int idx = tid + it2 * 512;          // 8-block index
            int s0 = SKB(8 * idx) >> 1;         // float4 index (16B-aligned)
            float2 q[8];
#pragma unroll
            for (int j = 0; j < 4; j++) {
                float4 v = zc4[s0 + j];
                q[2 * j]     = make_float2(v.x, v.y);
                q[2 * j + 1] = make_float2(v.z, v.w);
            }
            fwd8_r0(q);
#pragma unroll
            for (int j = 0; j < 4; j++) {
                float4 kk = __ldg(&K4[4 * idx + j]);
                q[2 * j]     = cmul(q[2 * j],     make_float2(kk.x, kk.y));
                q[2 * j + 1] = cmul(q[2 * j + 1], make_float2(kk.z, kk.w));
            }
            inv8_r0(q);
#pragma unroll
            for (int j = 0; j < 4; j++)
                zc4[s0 + j] = make_float4(q[2 * j].x, q[2 * j].y,
                                          q[2 * j + 1].x, q[2 * j + 1].y);
        }
    }
    __syncwarp();                              // exchange within 8-thread groups
    shared_pass<8, 3, false>(zc, lutC, tid);   // m = 16,32,64
    __syncthreads();
    shared_pass<64, 6, false>(zc, lutB, tid);  // m = 128,256,512
    __syncthreads();

    // I1: radix-16 s=512 (m=1024..8192), scale, D-skip (u reloaded), tanh
    {
        float Dh = D[h];
        const float sc = 1.f / 8192.f;
        float2 p[16];
#pragma unroll
        for (int c = 0; c < 16; c++) p[c] = zc[SKB(tid + c * 512)];
        inv16w(p, conjf2(lutA[tid]));
#pragma unroll
        for (int c = 0; c < 16; c++) {
            int n = tid + c * 512;
            o1[n] = ftanh(p[c].x * sc + Dh * u1[n]);
            o2[n] = ftanh(p[c].y * sc + Dh * u2[n]);
        }
    }
}

extern "C" void kernel_launch(void* const* d_in, const int* in_sizes, int n_in,
                              void* d_out, int out_size)
{
    const float* u     = (const float*)d_in[0];
    const float* A_re  = (const float*)d_in[1];
    const float* A_im  = (const float*)d_in[2];
    const float* BC_re = (const float*)d_in[3];
    const float* BC_im = (const float*)d_in[4];
    const float* D     = (const float*)d_in[5];

    const int MAIN_SMEM = (584 + 9216) * 8;   // 78400 bytes

    cudaFuncSetAttribute(kernel_spectrum, cudaFuncAttributeMaxDynamicSharedMemorySize, 98304);
    cudaFuncSetAttribute(fftconv_main, cudaFuncAttributeMaxDynamicSharedMemorySize, MAIN_SMEM);

    kernel_spectrum<<<dim3(65, 4), 512, 98304>>>(A_re, A_im, BC_re, BC_im);
    fftconv_main<<<Bn / 2 * Hn, 512, MAIN_SMEM>>>(u, D, (float*)d_out);
}

// round 16
// speedup vs baseline: 1.0175x; 1.0043x over previous
#include <cuda_runtime.h>
#include <math.h>

#define Ln 8192
#define Hn 256
#define Bn 16
#define Pn 64

// Krs spectrum, bit-reversed order per h.
__device__ float4 g_Krs4[Hn * Ln / 2];   // 16MB

#define TWO_PI 6.283185307179586f

__device__ __forceinline__ float2 cmul(float2 a, float2 b) {
    return make_float2(a.x * b.x - a.y * b.y, a.x * b.y + a.y * b.x);
}
__device__ __forceinline__ float2 cadd(float2 a, float2 b) { return make_float2(a.x + b.x, a.y + b.y); }
__device__ __forceinline__ float2 csub(float2 a, float2 b) { return make_float2(a.x - b.x, a.y - b.y); }
__device__ __forceinline__ float2 mulnegI(float2 a) { return make_float2(a.y, -a.x); }
__device__ __forceinline__ float2 mulposI(float2 a) { return make_float2(-a.y, a.x); }
__device__ __forceinline__ float2 conjf2(float2 a) { return make_float2(a.x, -a.y); }

// e^{i*2*pi*t} via fast MUFU trig; t re-centered to (-0.5, 0.5].
__device__ __forceinline__ float2 cis2pi(float t) {
    t -= rintf(t);
    float s, c; __sincosf(TWO_PI * t, &s, &c);
    return make_float2(c, s);
}

__device__ __forceinline__ float ftanh(float x) {
    float e = __expf(2.f * x);
    return 1.f - __fdividef(2.f, e + 1.f);
}

// ---------------------------------------------------------------------------
// Kernel 1: Krs_br[h, q] = Krs[h, bitrev13(q)].
// Phase-1 trig dedup: w depends only on fj (64 distinct values per class) —
// one accurate sincos table per CTA, then pure-rational G fills.
// ---------------------------------------------------------------------------
__global__ void __launch_bounds__(512) kernel_spectrum(
    const float* __restrict__ A_re, const float* __restrict__ A_im,
    const float* __restrict__ BC_re, const float* __restrict__ BC_im)
{
    extern __shared__ char smemK[];
    float4* G4  = (float4*)smemK;                // [64 p][64 fj]        64KB
    float4* ABT = (float4*)(smemK + 65536);      // [64 p][32 h-pairs]   32KB
    float2* wtab = (float2*)(smemK + 98304);     // [64 fj]              512B

    int t = threadIdx.x;
    int h0 = blockIdx.y * 64;
    int f0c = blockIdx.x;              // 0..64
    bool has_mirror = (f0c != 0) && (f0c != 64);

    // Phase 0: 64 accurate w values (denominators can be small -> accurate trig)
    if (t < 64) {
        int f = f0c + 128 * t;
        int fm = (f > 4096) ? f - Ln : f;
        float ang = (TWO_PI / (float)Ln) * (float)fm;
        float sn, cs; sincosf(ang, &sn, &cs);
        wtab[t] = make_float2(cs, -sn);          // w = e^{-i ang}
    }
    // ABT: [p][hl] = (Re BC, -Re(BC conj A)) for local h (no dependence on wtab)
    for (int idx = t; idx < 64 * 64; idx += 512) {
        int hl = idx >> 6, p = idx & 63;
        float br = BC_re[(h0 + hl) * Pn + p];
        float bi = BC_im[(h0 + hl) * Pn + p];
        float Ar = A_re[p], Ai = A_im[p];
        ((float2*)ABT)[p * 64 + hl] = make_float2(br, -(br * Ar + bi * Ai));
    }
    __syncthreads();

    // Phase 1: resolvent tile (1/d, w/d) — rational only, no trig.
    for (int idx = t; idx < 4096; idx += 512) {
        int p = idx >> 6, fj = idx & 63;
        float2 wv = wtab[fj];
        float wr = wv.x, wi = wv.y;
        float Ar = A_re[p], Ai = A_im[p];
        float g = 2.f * Ar;
        float dl = Ar * Ar + Ai * Ai;
        float w2r = wr * wr - wi * wi;
        float w2i = 2.f * wr * wi;
        float dr = 1.f - g * wr + dl * w2r;
        float di = -g * wi + dl * w2i;
        float iv = 1.f / (dr * dr + di * di);
        float cr = dr * iv, ci = -di * iv;        // 1/d
        float qr = wr * cr - wi * ci;             // w/d
        float qi = wr * ci + wi * cr;
        G4[idx] = make_float4(cr, ci, qr, qi);
    }
    __syncthreads();

    int tx = t & 63, tg = t >> 6;   // tx = fj; tg in [0,8): 8 h each
    float2 acc[8];
#pragma unroll
    for (int i = 0; i < 8; i++) acc[i] = make_float2(0.f, 0.f);

#pragma unroll 4
    for (int p = 0; p < 64; p++) {
        float4 g = G4[p * 64 + tx];
#pragma unroll
        for (int i = 0; i < 4; i++) {
            float4 ab2 = ABT[p * 32 + tg * 4 + i];
            acc[2 * i].x     += ab2.x * g.x + ab2.y * g.z;
            acc[2 * i].y     += ab2.x * g.y + ab2.y * g.w;
            acc[2 * i + 1].x += ab2.z * g.x + ab2.w * g.z;
            acc[2 * i + 1].y += ab2.z * g.y + ab2.w * g.w;
        }
    }
    __syncthreads();

    float2* stg1 = (float2*)smemK;               // [64 h][64 q]
    float2* stg2 = stg1 + 4096;                  // mirror (conj)
    int off = (int)(__brev((unsigned)tx) >> 26); // brev6(fj)
#pragma unroll
    for (int i = 0; i < 8; i++) {
        int row = tg * 8 + i;
        stg1[row * 64 + off] = acc[i];
        if (has_mirror)
            stg2[row * 64 + (63 - off)] = make_float2(acc[i].x, -acc[i].y);
    }
    __syncthreads();

    float2* Krs = (float2*)g_Krs4;
    int qb1 = (int)(__brev((unsigned)f0c) >> 25) * 64;
    for (int idx = t; idx < 4096; idx += 512) {
        int h = idx >> 6;
        Krs[(size_t)(h0 + h) * Ln + qb1 + (idx & 63)] = stg1[idx];
    }
    if (has_mirror) {
        int qb2 = (int)(__brev((unsigned)(128 - f0c)) >> 25) * 64;
        for (int idx = t; idx < 4096; idx += 512) {
            int h = idx >> 6;
            Krs[(size_t)(h0 + h) * Ln + qb2 + (idx & 63)] = stg2[idx];
        }
    }
}

// ---------------------------------------------------------------------------
// Kernel 2: FFT conv main. 13 stages = radix16(ends) + radix8(mid) + 8-contig F5.
// F5 Krs loads hoisted before the transform to overlap L2 latency.
// ---------------------------------------------------------------------------
#define SKB(i) ((i) + (((i) >> 4) << 1))
#define RHv 0.70710678118654752f
#define C16v 0.92387953251128675f   // cos(pi/8)
#define S16v 0.38268343236508977f   // sin(pi/8)

__device__ __forceinline__ void bf_dif(float2& a, float2& b, float2 w) {
    float2 t = csub(a, b); a = cadd(a, b); b = cmul(t, w);
}
__device__ __forceinline__ void bf_dit(float2& a, float2& b, float2 w) {
    float2 t = cmul(b, w); b = csub(a, t); a = cadd(a, t);
}
__device__ __forceinline__ void bf1_dif(float2& a, float2& b) {
    float2 t = csub(a, b); a = cadd(a, b); b = t;
}
__device__ __forceinline__ void bf1_dit(float2& a, float2& b) {
    float2 t = b; b = csub(a, t); a = cadd(a, t);
}

// 3 DIF radix-2 stages (m = 8s, 4s, 2s); twiddle base w1.
__device__ __forceinline__ void fwd8w(float2* p, float2 w1) {
    float2 w2 = cmul(w1, w1);
    float2 w4 = cmul(w2, w2);
    float2 w1b = cmul(w1, make_float2(RHv, -RHv));
    bf_dif(p[0], p[4], w1);
    bf_dif(p[1], p[5], w1b);
    bf_dif(p[2], p[6], mulnegI(w1));
    bf_dif(p[3], p[7], mulnegI(w1b));
    float2 w2b = mulnegI(w2);
    bf_dif(p[0], p[2], w2);  bf_dif(p[1], p[3], w2b);
    bf_dif(p[4], p[6], w2);  bf_dif(p[5], p[7], w2b);
    bf_dif(p[0], p[1], w4);  bf_dif(p[2], p[3], w4);
    bf_dif(p[4], p[5], w4);  bf_dif(p[6], p[7], w4);
}

// 3 DIT radix-2 stages (m = 2s, 4s, 8s); inverse twiddle base v1.
__device__ __forceinline__ void inv8w(float2* p, float2 v1) {
    float2 v2 = cmul(v1, v1);
    float2 v4 = cmul(v2, v2);
    bf_dit(p[0], p[1], v4);  bf_dit(p[2], p[3], v4);
    bf_dit(p[4], p[5], v4);  bf_dit(p[6], p[7], v4);
    float2 v2b = mulposI(v2);
    bf_dit(p[0], p[2], v2);  bf_dit(p[1], p[3], v2b);
    bf_dit(p[4], p[6], v2);  bf_dit(p[5], p[7], v2b);
    float2 v1b = cmul(v1, make_float2(RHv, RHv));
    bf_dit(p[0], p[4], v1);
    bf_dit(p[1], p[5], v1b);
    bf_dit(p[2], p[6], mulposI(v1));
    bf_dit(p[3], p[7], mulposI(v1b));
}

// 4 DIF stages over 16 points at one stride; base twiddle w1.
__device__ __forceinline__ void fwd16w(float2* p, float2 w1) {
    float2 a1 = cmul(w1, make_float2(C16v, -S16v));
    float2 a2 = cmul(w1, make_float2(RHv, -RHv));
    float2 a3 = cmul(w1, make_float2(S16v, -C16v));
    bf_dif(p[0], p[8],  w1);
    bf_dif(p[1], p[9],  a1);
    bf_dif(p[2], p[10], a2);
    bf_dif(p[3], p[11], a3);
    bf_dif(p[4], p[12], mulnegI(w1));
    bf_dif(p[5], p[13], mulnegI(a1));
    bf_dif(p[6], p[14], mulnegI(a2));
    bf_dif(p[7], p[15], mulnegI(a3));
    float2 w2 = cmul(w1, w1);
    fwd8w(p, w2);
    fwd8w(p + 8, w2);
}

// 4 DIT stages over 16 points at one stride; inverse base twiddle v1.
__device__ __forceinline__ void inv16w(float2* p, float2 v1) {
    float2 v2 = cmul(v1, v1);
    inv8w(p, v2);
    inv8w(p + 8, v2);
    float2 b1 = cmul(v1, make_float2(C16v, S16v));
    float2 b2 = cmul(v1, make_float2(RHv, RHv));
    float2 b3 = cmul(v1, make_float2(S16v, C16v));
    bf_dit(p[0], p[8],  v1);
    bf_dit(p[1], p[9],  b1);
    bf_dit(p[2], p[10], b2);
    bf_dit(p[3], p[11], b3);
    bf_dit(p[4], p[12], mulposI(v1));
    bf_dit(p[5], p[13], mulposI(b1));
    bf_dit(p[6], p[14], mulposI(b2));
    bf_dit(p[7], p[15], mulposI(b3));
}

// Constant-twiddle contiguous 8-point DIF (m=8,4,2), r=0.
__device__ __forceinline__ void fwd8_r0(float2* p) {
    bf1_dif(p[0], p[4]);
    bf_dif(p[1], p[5], make_float2(RHv, -RHv));
    { float2 t = csub(p[2], p[6]); p[2] = cadd(p[2], p[6]); p[6] = mulnegI(t); }
    bf_dif(p[3], p[7], make_float2(-RHv, -RHv));
    bf1_dif(p[0], p[2]);
    { float2 t = csub(p[1], p[3]); p[1] = cadd(p[1], p[3]); p[3] = mulnegI(t); }
    bf1_dif(p[4], p[6]);
    { float2 t = csub(p[5], p[7]); p[5] = cadd(p[5], p[7]); p[7] = mulnegI(t); }
    bf1_dif(p[0], p[1]); bf1_dif(p[2], p[3]);
    bf1_dif(p[4], p[5]); bf1_dif(p[6], p[7]);
}

// Constant-twiddle contiguous 8-point DIT (m=2,4,8), r=0.
__device__ __forceinline__ void inv8_r0(float2* p) {
    bf1_dit(p[0], p[1]); bf1_dit(p[2], p[3]);
    bf1_dit(p[4], p[5]); bf1_dit(p[6], p[7]);
    bf1_dit(p[0], p[2]);
    { float2 t = mulposI(p[3]); p[3] = csub(p[1], t); p[1] = cadd(p[1], t); }
    bf1_dit(p[4], p[6]);
    { float2 t = mulposI(p[7]); p[7] = csub(p[5], t); p[5] = cadd(p[5], t); }
    bf1_dit(p[0], p[4]);
    bf_dit(p[1], p[5], make_float2(RHv, RHv));
    { float2 t = mulposI(p[6]); p[6] = csub(p[2], t); p[2] = cadd(p[2], t); }
    bf_dit(p[3], p[7], make_float2(-RHv, RHv));
}

// Radix-8 shared pass: lut[r] = e^{-2pi i r/(8S)}.
template <int S, int LS, bool FWD>
__device__ __forceinline__ void shared_pass(float2* z, const float2* lut, int tid) {
#pragma unroll
    for (int it2 = 0; it2 < 2; it2++) {
        int it = tid + it2 * 512;
        int r = it & (S - 1);
        int base = ((it >> LS) << (LS + 3)) + r;
        float2 w1 = lut[r];
        if (!FWD) w1 = conjf2(w1);
        float2 p[8];
#pragma unroll
        for (int c = 0; c < 8; c++) p[c] = z[SKB(base + c * S)];
        if (FWD) fwd8w(p, w1);
        else     inv8w(p, w1);
#pragma unroll
        for (int c = 0; c < 8; c++) z[SKB(base + c * S)] = p[c];
    }
}

__global__ void __launch_bounds__(512, 2) fftconv_main(
    const float* __restrict__ u, const float* __restrict__ D,
    float* __restrict__ out)
{
    extern __shared__ float2 sm[];
    float2* lutA = sm;                 // 512 : e^{-2pi i r/8192}, r<512
    float2* lutB = sm + 512;           // 64  : e^{-2pi i r/512}
    float2* lutC = sm + 576;           // 8   : e^{-2pi i r/64}
    float2* zc   = sm + 584;           // 9216 float2 (skewed 8192)

    int blk = blockIdx.x;
    int h = blk >> 3, pb = blk & 7;
    const float* u1 = u + ((size_t)(2 * pb) * Hn + h) * Ln;
    const float* u2 = u + ((size_t)(2 * pb + 1) * Hn + h) * Ln;
    float* o1 = out + ((size_t)(2 * pb) * Hn + h) * Ln;
    float* o2 = out + ((size_t)(2 * pb + 1) * Hn + h) * Ln;
    int tid = threadIdx.x;

    // Twiddle LUT init
    lutA[tid] = cis2pi(-(float)tid * (1.f / 8192.f));
    if (tid < 64) lutB[tid] = cis2pi(-(float)tid * (1.f / 512.f));
    if (tid < 8)  lutC[tid] = cis2pi(-(float)tid * (1.f / 64.f));
    __syncthreads();

    // F1: load z = u1 + i*u2, radix-16 s=512 (m=8192,4096,2048,1024)
    {
        float2 p[16];
#pragma unroll
        for (int c = 0; c < 16; c++) {
            int n = tid + c * 512;
            p[c] = make_float2(u1[n], u2[n]);
        }
        fwd16w(p, lutA[tid]);
#pragma unroll
        for (int c = 0; c < 16; c++) zc[SKB(tid + c * 512)] = p[c];
    }
    __syncthreads();
    shared_pass<64, 6, true>(zc, lutB, tid);   // m = 512,256,128
    __syncthreads();
    shared_pass<8, 3, true>(zc, lutC, tid);    // m = 64,32,16
    __syncwarp();                              // exchange within 8-thread groups

    // F5: 8 contiguous points: fwd m=8,4,2 -> *Krs(bitrev) -> inv m=2,4,8
    // K loads issued FIRST to overlap L2/DRAM latency with the transform.
    {
        const float4* K4 = g_Krs4 + (size_t)h * (Ln / 2);
        float4* zc4 = (float4*)zc;
#pragma unroll
        for (int it2 = 0; it2 < 2; it2++) {
            int idx = tid + it2 * 512;          // 8-block index
            int s0 = SKB(8 * idx) >> 1;         // float4 index (16B-aligned)
            float4 kk[4];
#pragma unroll
            for (int j = 0; j < 4; j++) kk[j] = __ldg(&K4[4 * idx + j]);
            float2 q[8];
#pragma unroll
            for (int j = 0; j < 4; j++) {
                float4 v = zc4[s0 + j];
                q[2 * j]     = make_float2(v.x, v.y);
                q[2 * j + 1] = make_float2(v.z, v.w);
            }
            fwd8_r0(q);
#pragma unroll
            for (int j = 0; j < 4; j++) {
                q[2 * j]     = cmul(q[2 * j],     make_float2(kk[j].x, kk[j].y));
                q[2 * j + 1] = cmul(q[2 * j + 1], make_float2(kk[j].z, kk[j].w));
            }
            inv8_r0(q);
#pragma unroll
            for (int j = 0; j < 4; j++)
                zc4[s0 + j] = make_float4(q[2 * j].x, q[2 * j].y,
                                          q[2 * j + 1].x, q[2 * j + 1].y);
        }
    }
    __syncwarp();                              // exchange within 8-thread groups
    shared_pass<8, 3, false>(zc, lutC, tid);   // m = 16,32,64
    __syncthreads();
    shared_pass<64, 6, false>(zc, lutB, tid);  // m = 128,256,512
    __syncthreads();

    // I1: radix-16 s=512 (m=1024..8192), scale, D-skip (u reloaded), tanh
    {
        float Dh = D[h];
        const float sc = 1.f / 8192.f;
        float2 p[16];
#pragma unroll
        for (int c = 0; c < 16; c++) p[c] = zc[SKB(tid + c * 512)];
        inv16w(p, conjf2(lutA[tid]));
#pragma unroll
        for (int c = 0; c < 16; c++) {
            int n = tid + c * 512;
            o1[n] = ftanh(p[c].x * sc + Dh * u1[n]);
            o2[n] = ftanh(p[c].y * sc + Dh * u2[n]);
        }
    }
}

extern "C" void kernel_launch(void* const* d_in, const int* in_sizes, int n_in,
                              void* d_out, int out_size)
{
    const float* u     = (const float*)d_in[0];
    const float* A_re  = (const float*)d_in[1];
    const float* A_im  = (const float*)d_in[2];
    const float* BC_re = (const float*)d_in[3];
    const float* BC_im = (const float*)d_in[4];
    const float* D     = (const float*)d_in[5];

    const int MAIN_SMEM = (584 + 9216) * 8;   // 78400 bytes
    const int SPEC_SMEM = 98304 + 512;        // G4 + ABT + wtab

    cudaFuncSetAttribute(kernel_spectrum, cudaFuncAttributeMaxDynamicSharedMemorySize, SPEC_SMEM);
    cudaFuncSetAttribute(fftconv_main, cudaFuncAttributeMaxDynamicSharedMemorySize, MAIN_SMEM);

    kernel_spectrum<<<dim3(65, 4), 512, SPEC_SMEM>>>(A_re, A_im, BC_re, BC_im);
    fftconv_main<<<Bn / 2 * Hn, 512, MAIN_SMEM>>>(u, D, (float*)d_out);
}